// round 8
// baseline (speedup 1.0000x reference)
#include <cuda_runtime.h>

#define NUM_CLS 32000
#define BATCH   4096
#define C4      (NUM_CLS / 4)   // 8000 float4 per row
#define THREADS 512
#define NWARP   (THREADS / 32)  // 16

// Per-row partial results (deterministic; no float atomics).
__device__ float g_row[BATCH];
// Completion counter; last block resets it so graph replays start clean.
__device__ unsigned int g_done;

__global__ __launch_bounds__(THREADS, 4)
void rce_fused_kernel(const float* __restrict__ inp,
                      const float* __restrict__ tgt,
                      float* __restrict__ out)
{
    const int row = blockIdx.x;
    const float4* ip = reinterpret_cast<const float4*>(inp + (size_t)row * NUM_CLS);
    const float4* tp = reinterpret_cast<const float4*>(tgt + (size_t)row * NUM_CLS);

    // ---- Pass 1: stream the input row -> S = sum x, E = sum exp(-x) ----
    float s_sum = 0.f;
    float e_sum = 0.f;
    #pragma unroll 8
    for (int i = threadIdx.x; i < C4; i += THREADS) {
        const float4 x = ip[i];
        s_sum += (x.x + x.y) + (x.z + x.w);
        e_sum += (__expf(-x.x) + __expf(-x.y)) + (__expf(-x.z) + __expf(-x.w));
    }

    // ---- Pass 2: stream the target row -> argmin (first index on ties) ----
    unsigned cur_bits = 0xffffffffu;   // t >= 0 -> float bits order-preserving
    unsigned cur_idx  = 0u;
    #pragma unroll 8
    for (int i = threadIdx.x; i < C4; i += THREADS) {
        const float4 t = tp[i];
        const unsigned b0 = __float_as_uint(t.x);
        const unsigned b1 = __float_as_uint(t.y);
        const unsigned b2 = __float_as_uint(t.z);
        const unsigned b3 = __float_as_uint(t.w);
        // Quad-local argmin, first index wins ties.
        const unsigned m01 = min(b0, b1);
        const unsigned i01 = (b1 < b0) ? 1u : 0u;
        const unsigned m23 = min(b2, b3);
        const unsigned i23 = (b3 < b2) ? 3u : 2u;
        const unsigned m   = min(m01, m23);
        const unsigned iq  = (m23 < m01) ? i23 : i01;
        // Iterations ascend per thread -> strict < keeps earlier index on tie.
        if (m < cur_bits) { cur_bits = m; cur_idx = (unsigned)i * 4u + iq; }
    }

    // Warp reduce. Value tie -> smaller index (global first occurrence).
    #pragma unroll
    for (int o = 16; o > 0; o >>= 1) {
        s_sum += __shfl_xor_sync(0xffffffffu, s_sum, o);
        e_sum += __shfl_xor_sync(0xffffffffu, e_sum, o);
        const unsigned ob = __shfl_xor_sync(0xffffffffu, cur_bits, o);
        const unsigned oi = __shfl_xor_sync(0xffffffffu, cur_idx,  o);
        if (ob < cur_bits || (ob == cur_bits && oi < cur_idx)) {
            cur_bits = ob; cur_idx = oi;
        }
    }

    __shared__ float    sh_s[NWARP];
    __shared__ float    sh_e[NWARP];
    __shared__ unsigned sh_b[NWARP];
    __shared__ unsigned sh_i[NWARP];
    __shared__ bool     sh_last;
    const int wid = threadIdx.x >> 5;
    const int lid = threadIdx.x & 31;
    if (lid == 0) { sh_s[wid] = s_sum; sh_e[wid] = e_sum;
                    sh_b[wid] = cur_bits; sh_i[wid] = cur_idx; }
    __syncthreads();

    // Warp 0 combines the NWARP(=16) partials with shuffles.
    if (wid == 0) {
        const bool live = (lid < NWARP);
        float S = live ? sh_s[lid] : 0.f;
        float E = live ? sh_e[lid] : 0.f;
        unsigned B = live ? sh_b[lid] : 0xffffffffu;
        unsigned I = live ? sh_i[lid] : 0xffffffffu;
        #pragma unroll
        for (int o = 8; o > 0; o >>= 1) {
            S += __shfl_xor_sync(0xffffffffu, S, o);
            E += __shfl_xor_sync(0xffffffffu, E, o);
            const unsigned ob = __shfl_xor_sync(0xffffffffu, B, o);
            const unsigned oi = __shfl_xor_sync(0xffffffffu, I, o);
            if (ob < B || (ob == B && oi < I)) { B = ob; I = oi; }
        }
        if (lid == 0) {
            const float xi = inp[(size_t)row * NUM_CLS + I];
            // r_b = S_b + (C-1)*log(E_b) - x[b, idx]
            g_row[row] = S + (float)(NUM_CLS - 1) * logf(E) - xi;

            __threadfence();
            const unsigned prev = atomicAdd(&g_done, 1u);
            sh_last = (prev == (unsigned)(BATCH - 1));
        }
    }
    __syncthreads();

    // Last block performs the final deterministic reduction (g_row L2-hot).
    if (sh_last) {
        float s = 0.f;
        for (int i = threadIdx.x; i < BATCH; i += THREADS)
            s += __ldcg(&g_row[i]);

        #pragma unroll
        for (int o = 16; o > 0; o >>= 1)
            s += __shfl_xor_sync(0xffffffffu, s, o);

        __shared__ float sh_f[NWARP];
        if (lid == 0) sh_f[wid] = s;
        __syncthreads();

        if (wid == 0) {
            float tot = (lid < NWARP) ? sh_f[lid] : 0.f;
            #pragma unroll
            for (int o = 8; o > 0; o >>= 1)
                tot += __shfl_xor_sync(0xffffffffu, tot, o);
            if (lid == 0) {
                // loss = (RATIO / (B*(C-1))) * sum_b r_b ; RATIO = 1.0
                out[0] = tot * (1.0f / ((float)BATCH * (float)(NUM_CLS - 1)));
                g_done = 0;   // reset for next graph replay
            }
        }
    }
}

extern "C" void kernel_launch(void* const* d_in, const int* in_sizes, int n_in,
                              void* d_out, int out_size)
{
    const float* inp = (const float*)d_in[0];   // input  [B, C] f32
    const float* tgt = (const float*)d_in[1];   // target [B, C] f32
    float* out = (float*)d_out;                 // scalar f32

    rce_fused_kernel<<<BATCH, THREADS>>>(inp, tgt, out);
}

// round 9
// speedup vs baseline: 1.0919x; 1.0919x over previous
#include <cuda_runtime.h>

#define NUM_CLS 32000
#define BATCH   4096
#define C4      (NUM_CLS / 4)   // 8000 float4 per row
#define THREADS 512
#define NWARP   (THREADS / 32)  // 16
#define NBLOCKS 592             // 148 SMs x 4 resident CTAs — persistent grid

// Per-row partial results (deterministic; no float atomics).
__device__ float g_row[BATCH];
// Completion counter; last block resets it so graph replays start clean.
__device__ unsigned int g_done;

__global__ __launch_bounds__(THREADS, 4)
void rce_fused_kernel(const float* __restrict__ inp,
                      const float* __restrict__ tgt,
                      float* __restrict__ out)
{
    const int wid = threadIdx.x >> 5;
    const int lid = threadIdx.x & 31;

    __shared__ float    sh_s[NWARP];
    __shared__ float    sh_e[NWARP];
    __shared__ unsigned sh_b[NWARP];
    __shared__ unsigned sh_i[NWARP];
    __shared__ bool     sh_last;

    // Persistent loop: each block handles rows bid, bid+592, ...
    for (int row = blockIdx.x; row < BATCH; row += NBLOCKS) {
        const float4* ip = reinterpret_cast<const float4*>(inp + (size_t)row * NUM_CLS);
        const float4* tp = reinterpret_cast<const float4*>(tgt + (size_t)row * NUM_CLS);

        float s_sum = 0.f;                 // sum of x
        float e_sum = 0.f;                 // sum of exp(-x)
        unsigned cur_bits = 0xffffffffu;   // running min of target bits (t >= 0
        unsigned cur_idx  = 0u;            //  -> float bits order-preserving)

        #pragma unroll 4
        for (int i = threadIdx.x; i < C4; i += THREADS) {
            const float4 x = ip[i];
            const float4 t = tp[i];

            s_sum += (x.x + x.y) + (x.z + x.w);
            e_sum += (__expf(-x.x) + __expf(-x.y)) + (__expf(-x.z) + __expf(-x.w));

            const unsigned b0 = __float_as_uint(t.x);
            const unsigned b1 = __float_as_uint(t.y);
            const unsigned b2 = __float_as_uint(t.z);
            const unsigned b3 = __float_as_uint(t.w);
            // Quad-local argmin, first index wins ties.
            const unsigned m01 = min(b0, b1);
            const unsigned i01 = (b1 < b0) ? 1u : 0u;
            const unsigned m23 = min(b2, b3);
            const unsigned i23 = (b3 < b2) ? 3u : 2u;
            const unsigned m   = min(m01, m23);
            const unsigned iq  = (m23 < m01) ? i23 : i01;
            // Iterations ascend per thread -> strict < keeps earlier index.
            if (m < cur_bits) { cur_bits = m; cur_idx = (unsigned)i * 4u + iq; }
        }

        // Warp reduce. Value tie -> smaller index (global first occurrence).
        #pragma unroll
        for (int o = 16; o > 0; o >>= 1) {
            s_sum += __shfl_xor_sync(0xffffffffu, s_sum, o);
            e_sum += __shfl_xor_sync(0xffffffffu, e_sum, o);
            const unsigned ob = __shfl_xor_sync(0xffffffffu, cur_bits, o);
            const unsigned oi = __shfl_xor_sync(0xffffffffu, cur_idx,  o);
            if (ob < cur_bits || (ob == cur_bits && oi < cur_idx)) {
                cur_bits = ob; cur_idx = oi;
            }
        }

        if (lid == 0) { sh_s[wid] = s_sum; sh_e[wid] = e_sum;
                        sh_b[wid] = cur_bits; sh_i[wid] = cur_idx; }
        __syncthreads();

        // Warp 0 combines the NWARP(=16) partials with shuffles.
        if (wid == 0) {
            const bool live = (lid < NWARP);
            float S = live ? sh_s[lid] : 0.f;
            float E = live ? sh_e[lid] : 0.f;
            unsigned B = live ? sh_b[lid] : 0xffffffffu;
            unsigned I = live ? sh_i[lid] : 0xffffffffu;
            #pragma unroll
            for (int o = 8; o > 0; o >>= 1) {
                S += __shfl_xor_sync(0xffffffffu, S, o);
                E += __shfl_xor_sync(0xffffffffu, E, o);
                const unsigned ob = __shfl_xor_sync(0xffffffffu, B, o);
                const unsigned oi = __shfl_xor_sync(0xffffffffu, I, o);
                if (ob < B || (ob == B && oi < I)) { B = ob; I = oi; }
            }
            if (lid == 0) {
                const float xi = inp[(size_t)row * NUM_CLS + I];
                // r_b = S_b + (C-1)*log(E_b) - x[b, idx]
                g_row[row] = S + (float)(NUM_CLS - 1) * logf(E) - xi;
            }
        }
        __syncthreads();   // smem reused next row iteration
    }

    // Block done with all its rows: publish and count.
    if (threadIdx.x == 0) {
        __threadfence();
        const unsigned prev = atomicAdd(&g_done, 1u);
        sh_last = (prev == (unsigned)(NBLOCKS - 1));
    }
    __syncthreads();

    // Last block performs the final deterministic reduction (g_row L2-hot).
    if (sh_last) {
        float s = 0.f;
        for (int i = threadIdx.x; i < BATCH; i += THREADS)
            s += __ldcg(&g_row[i]);

        #pragma unroll
        for (int o = 16; o > 0; o >>= 1)
            s += __shfl_xor_sync(0xffffffffu, s, o);

        __shared__ float sh_f[NWARP];
        if (lid == 0) sh_f[wid] = s;
        __syncthreads();

        if (wid == 0) {
            float tot = (lid < NWARP) ? sh_f[lid] : 0.f;
            #pragma unroll
            for (int o = 8; o > 0; o >>= 1)
                tot += __shfl_xor_sync(0xffffffffu, tot, o);
            if (lid == 0) {
                // loss = (RATIO / (B*(C-1))) * sum_b r_b ; RATIO = 1.0
                out[0] = tot * (1.0f / ((float)BATCH * (float)(NUM_CLS - 1)));
                g_done = 0;   // reset for next graph replay
            }
        }
    }
}

extern "C" void kernel_launch(void* const* d_in, const int* in_sizes, int n_in,
                              void* d_out, int out_size)
{
    const float* inp = (const float*)d_in[0];   // input  [B, C] f32
    const float* tgt = (const float*)d_in[1];   // target [B, C] f32
    float* out = (float*)d_out;                 // scalar f32

    rce_fused_kernel<<<NBLOCKS, THREADS>>>(inp, tgt, out);
}

// round 10
// speedup vs baseline: 1.0966x; 1.0043x over previous
#include <cuda_runtime.h>

#define NUM_CLS 32000
#define BATCH   4096
#define C4      (NUM_CLS / 4)   // 8000 float4 per row
#define THREADS 512
#define NWARP   (THREADS / 32)  // 16
#define NBLOCKS 592             // 148 SMs x 4 resident CTAs — persistent grid

// Per-row partial results (deterministic; no float atomics).
__device__ float g_row[BATCH];
// Completion counter; last block resets it so graph replays start clean.
__device__ unsigned int g_done;

__global__ __launch_bounds__(THREADS, 4)
void rce_fused_kernel(const float* __restrict__ inp,
                      const float* __restrict__ tgt,
                      float* __restrict__ out)
{
    const int wid = threadIdx.x >> 5;
    const int lid = threadIdx.x & 31;

    // Double-buffered per-warp partials (parity = row counter & 1).
    // Correctness of reuse: buffer p written at row k is read by warp 0
    // after the row-k __syncthreads; warp 0 reaches the row-(k+1)
    // __syncthreads only after that read, and buffer p is next written at
    // row k+2, after all warps passed the row-(k+1) barrier. So the single
    // per-row barrier orders read-before-rewrite with no second barrier.
    __shared__ float    sh_s[2][NWARP];
    __shared__ float    sh_e[2][NWARP];
    __shared__ unsigned sh_b[2][NWARP];
    __shared__ unsigned sh_i[2][NWARP];
    __shared__ bool     sh_last;

    int k = 0;
    for (int row = blockIdx.x; row < BATCH; row += NBLOCKS, ++k) {
        const int p = k & 1;
        const float4* ip = reinterpret_cast<const float4*>(inp + (size_t)row * NUM_CLS);
        const float4* tp = reinterpret_cast<const float4*>(tgt + (size_t)row * NUM_CLS);

        float s_sum = 0.f;                 // sum of x
        float e_sum = 0.f;                 // sum of exp(-x)
        unsigned cur_bits = 0xffffffffu;   // running min of target bits (t >= 0
        unsigned cur_idx  = 0u;            //  -> float bits order-preserving)

        #pragma unroll 4
        for (int i = threadIdx.x; i < C4; i += THREADS) {
            const float4 x = ip[i];
            const float4 t = tp[i];

            s_sum += (x.x + x.y) + (x.z + x.w);
            e_sum += (__expf(-x.x) + __expf(-x.y)) + (__expf(-x.z) + __expf(-x.w));

            const unsigned b0 = __float_as_uint(t.x);
            const unsigned b1 = __float_as_uint(t.y);
            const unsigned b2 = __float_as_uint(t.z);
            const unsigned b3 = __float_as_uint(t.w);
            // Quad-local argmin, first index wins ties.
            const unsigned m01 = min(b0, b1);
            const unsigned i01 = (b1 < b0) ? 1u : 0u;
            const unsigned m23 = min(b2, b3);
            const unsigned i23 = (b3 < b2) ? 3u : 2u;
            const unsigned m   = min(m01, m23);
            const unsigned iq  = (m23 < m01) ? i23 : i01;
            // Iterations ascend per thread -> strict < keeps earlier index.
            if (m < cur_bits) { cur_bits = m; cur_idx = (unsigned)i * 4u + iq; }
        }

        // Warp reduce. Value tie -> smaller index (global first occurrence).
        #pragma unroll
        for (int o = 16; o > 0; o >>= 1) {
            s_sum += __shfl_xor_sync(0xffffffffu, s_sum, o);
            e_sum += __shfl_xor_sync(0xffffffffu, e_sum, o);
            const unsigned ob = __shfl_xor_sync(0xffffffffu, cur_bits, o);
            const unsigned oi = __shfl_xor_sync(0xffffffffu, cur_idx,  o);
            if (ob < cur_bits || (ob == cur_bits && oi < cur_idx)) {
                cur_bits = ob; cur_idx = oi;
            }
        }

        if (lid == 0) { sh_s[p][wid] = s_sum; sh_e[p][wid] = e_sum;
                        sh_b[p][wid] = cur_bits; sh_i[p][wid] = cur_idx; }
        __syncthreads();   // the ONLY per-row barrier

        // Warp 0 combines buffer p and retires the row while warps 1..15
        // stream the next row's loads.
        if (wid == 0) {
            const bool live = (lid < NWARP);
            float S = live ? sh_s[p][lid] : 0.f;
            float E = live ? sh_e[p][lid] : 0.f;
            unsigned B = live ? sh_b[p][lid] : 0xffffffffu;
            unsigned I = live ? sh_i[p][lid] : 0xffffffffu;
            #pragma unroll
            for (int o = 8; o > 0; o >>= 1) {
                S += __shfl_xor_sync(0xffffffffu, S, o);
                E += __shfl_xor_sync(0xffffffffu, E, o);
                const unsigned ob = __shfl_xor_sync(0xffffffffu, B, o);
                const unsigned oi = __shfl_xor_sync(0xffffffffu, I, o);
                if (ob < B || (ob == B && oi < I)) { B = ob; I = oi; }
            }
            if (lid == 0) {
                const float xi = inp[(size_t)row * NUM_CLS + I];
                // r_b = S_b + (C-1)*log(E_b) - x[b, idx]
                g_row[row] = S + (float)(NUM_CLS - 1) * logf(E) - xi;
            }
        }
        // no second __syncthreads — double buffering makes it unnecessary
    }

    // Block done with all its rows: publish and count. thread 0 (warp 0)
    // performed every g_row write of this block, so its fence covers them.
    if (threadIdx.x == 0) {
        __threadfence();
        const unsigned prev = atomicAdd(&g_done, 1u);
        sh_last = (prev == (unsigned)(NBLOCKS - 1));
    }
    __syncthreads();

    // Last block performs the final deterministic reduction (g_row L2-hot).
    if (sh_last) {
        float s = 0.f;
        for (int i = threadIdx.x; i < BATCH; i += THREADS)
            s += __ldcg(&g_row[i]);

        #pragma unroll
        for (int o = 16; o > 0; o >>= 1)
            s += __shfl_xor_sync(0xffffffffu, s, o);

        __shared__ float sh_f[NWARP];
        if (lid == 0) sh_f[wid] = s;
        __syncthreads();

        if (wid == 0) {
            float tot = (lid < NWARP) ? sh_f[lid] : 0.f;
            #pragma unroll
            for (int o = 8; o > 0; o >>= 1)
                tot += __shfl_xor_sync(0xffffffffu, tot, o);
            if (lid == 0) {
                // loss = (RATIO / (B*(C-1))) * sum_b r_b ; RATIO = 1.0
                out[0] = tot * (1.0f / ((float)BATCH * (float)(NUM_CLS - 1)));
                g_done = 0;   // reset for next graph replay
            }
        }
    }
}

extern "C" void kernel_launch(void* const* d_in, const int* in_sizes, int n_in,
                              void* d_out, int out_size)
{
    const float* inp = (const float*)d_in[0];   // input  [B, C] f32
    const float* tgt = (const float*)d_in[1];   // target [B, C] f32
    float* out = (float*)d_out;                 // scalar f32

    rce_fused_kernel<<<NBLOCKS, THREADS>>>(inp, tgt, out);
}